// round 1
// baseline (speedup 1.0000x reference)
#include <cuda_runtime.h>

// Who2com reduces algebraically to mean over the N (agent) axis:
// val_mat[b,k,q] = bevs[b,q]  (broadcast over key axis), and
// sum_k final[b,k,q] = 1 (softmax column sums), so
// out[b,c,h,w] = (1/N) * sum_n bevs[b,n,c,h,w].
//
// B=32, N=5, C=256, H=W=16.  CHW = 65536 floats = 16384 float4.
// out = 32 * 16384 float4 = 524288 float4.

static constexpr int B_ = 32;
static constexpr int N_ = 5;
static constexpr int CHW4 = 256 * 16 * 16 / 4;   // 16384 float4 per (b,n) slice
static constexpr int OUT4 = B_ * CHW4;           // 524288 float4

__global__ __launch_bounds__(256) void who2com_mean_kernel(
    const float4* __restrict__ bevs, float4* __restrict__ out)
{
    int idx = blockIdx.x * blockDim.x + threadIdx.x;   // 0 .. OUT4-1
    if (idx >= OUT4) return;

    int b   = idx >> 14;          // / CHW4
    int chw = idx & (CHW4 - 1);   // % CHW4

    const float4* base = bevs + (size_t)b * N_ * CHW4 + chw;

    float4 a0 = base[0 * CHW4];
    float4 a1 = base[1 * CHW4];
    float4 a2 = base[2 * CHW4];
    float4 a3 = base[3 * CHW4];
    float4 a4 = base[4 * CHW4];

    const float inv_n = 0.2f;
    float4 r;
    r.x = (a0.x + a1.x + a2.x + a3.x + a4.x) * inv_n;
    r.y = (a0.y + a1.y + a2.y + a3.y + a4.y) * inv_n;
    r.z = (a0.z + a1.z + a2.z + a3.z + a4.z) * inv_n;
    r.w = (a0.w + a1.w + a2.w + a3.w + a4.w) * inv_n;

    out[idx] = r;
}

extern "C" void kernel_launch(void* const* d_in, const int* in_sizes, int n_in,
                              void* d_out, int out_size)
{
    const float4* bevs = (const float4*)d_in[0];  // (B, N, C, H, W) fp32
    float4* out = (float4*)d_out;                 // (B, C, H, W) fp32

    const int threads = 256;
    const int blocks = (OUT4 + threads - 1) / threads;  // 2048
    who2com_mean_kernel<<<blocks, threads>>>(bevs, out);
}